// round 3
// baseline (speedup 1.0000x reference)
#include <cuda_runtime.h>

#define Bn 4
#define Nn 128
#define Cn 128
#define TFn 8
#define En 8192
#define NEGV (-1e9f)
#define EPB 16   // edges per block in GEMM kernels (8 warps x 2 edges)

// ---------------- scratch (static device globals; no allocation) ----------------
__device__ float g_msgE[Bn*Nn*Nn*Cn];
__device__ float g_T1[Bn*Nn*Nn*TFn];          // te1 transposed: [b][dst][src][f]
__device__ float g_T2[Bn*Nn*Nn*TFn];          // te2 transposed: [b][dst][src][f]
__device__ float g_te3[Bn*Nn*Nn*TFn];         // te3 normal:     [b][src][dst][f]
__device__ float g_msg1[Bn*Nn*Cn];
__device__ float g_msg2[Bn*Nn*Cn];
__device__ float g_u1[Bn*Nn*Cn];
__device__ float g_t1[Bn*Nn*TFn];
__device__ float g_t2[Bn*Nn*TFn];
__device__ float g_t3[Bn*Nn*TFn];
__device__ float g_mgg[Bn*Cn];
__device__ float g_tg[Bn*TFn];
__device__ unsigned g_maxacc[Bn*Nn*Cn];

// ---------------- helpers ----------------
__device__ __forceinline__ unsigned fmap(float f) {
    int i = __float_as_int(f);
    return (i >= 0) ? ((unsigned)i | 0x80000000u) : ~(unsigned)i;
}
__device__ __forceinline__ float funmap(unsigned u) {
    int i = (u & 0x80000000u) ? (int)(u & 0x7FFFFFFFu) : ~(int)u;
    return __int_as_float(i);
}
__device__ __forceinline__ float wredsum(float v) {
    #pragma unroll
    for (int o = 16; o; o >>= 1) v += __shfl_xor_sync(0xffffffffu, v, o);
    return v;
}
__device__ __forceinline__ float brsum(float v, float* sred, int t) {
    v = wredsum(v);
    if ((t & 31) == 0) sred[t >> 5] = v;
    __syncthreads();
    v = sred[0] + sred[1] + sred[2] + sred[3];
    __syncthreads();
    return v;
}
// packed dual-fp32 FMA (sm_103a FFMA2)
__device__ __forceinline__ void fma2(unsigned long long& acc,
                                     unsigned long long a, unsigned long long b) {
    asm("fma.rn.f32x2 %0, %1, %2, %0;" : "+l"(acc) : "l"(a), "l"(b));
}
__device__ __forceinline__ unsigned long long bcast2(float x) {
    unsigned long long r;
    asm("mov.b64 %0, {%1, %1};" : "=l"(r) : "f"(x));
    return r;
}
__device__ __forceinline__ float2 unpack2(unsigned long long v) {
    float2 r;
    asm("mov.b64 {%0, %1}, %2;" : "=f"(r.x), "=f"(r.y) : "l"(v));
    return r;
}

// ---------------- K1: init / zero (vectorized) ----------------
#define A4 (Bn*Nn*Nn*TFn/4)          // float4 per te buffer = 131072
#define B4 (En*32)                   // float4 for msgE edge slots = 262144
#define C4 (Bn*Nn*Cn/4)              // uint4 for maxacc = 16384
__global__ void k_init(const int* __restrict__ eidx) {
    int idx = blockIdx.x * 256 + threadIdx.x;
    const float4 z4 = {0.f, 0.f, 0.f, 0.f};
    if (idx < 3*A4) {
        if (idx < A4)            ((float4*)g_T1)[idx] = z4;
        else if (idx < 2*A4)     ((float4*)g_T2)[idx - A4] = z4;
        else                     ((float4*)g_te3)[idx - 2*A4] = z4;
    } else if (idx < 3*A4 + B4) {
        int r = idx - 3*A4;
        int e = r >> 5, o = r & 31;
        int sg = eidx[e], dg = eidx[En + e];
        int b = sg >> 7, s = sg & 127, d = dg & 127;
        ((float4*)g_msgE)[((b*Nn + s)*Nn + d)*32 + o] = z4;
    } else if (idx < 3*A4 + B4 + C4) {
        int r = idx - 3*A4 - B4;
        unsigned m = fmap(NEGV);
        uint4 mv = {m, m, m, m};
        ((uint4*)g_maxacc)[r] = mv;
    }
}

// ---------------- K2: node & graph projections ----------------
__global__ void k_proj(const float* __restrict__ node, const float* __restrict__ graph,
                       const float* __restrict__ Wm1, const float* __restrict__ Wm2,
                       const float* __restrict__ Wu1,
                       const float* __restrict__ Wt1, const float* __restrict__ Wt2,
                       const float* __restrict__ Wt3,
                       const float* __restrict__ Wmg, const float* __restrict__ Wtg) {
    __shared__ float sx[128];
    int blk = blockIdx.x, t = threadIdx.x;
    if (blk < Bn*Nn) {
        sx[t] = node[blk*128 + t];
        __syncthreads();
        float a1 = 0.f, a2 = 0.f, a3 = 0.f;
        #pragma unroll 8
        for (int f = 0; f < 128; f++) {
            float x = sx[f];
            a1 += x * Wm1[f*128 + t];
            a2 += x * Wm2[f*128 + t];
            a3 += x * Wu1[f*128 + t];
        }
        g_msg1[blk*128 + t] = a1;
        g_msg2[blk*128 + t] = a2;
        g_u1[blk*128 + t]   = a3;
        if (t < 24) {
            int jj = t & 7;
            const float* W = (t < 8) ? Wt1 : ((t < 16) ? Wt2 : Wt3);
            float a = 0.f;
            #pragma unroll 8
            for (int f = 0; f < 128; f++) a += sx[f] * W[f*8 + jj];
            float* dstp = (t < 8) ? g_t1 : ((t < 16) ? g_t2 : g_t3);
            dstp[blk*8 + jj] = a;
        }
    } else {
        int g = blk - Bn*Nn;
        sx[t] = graph[g*128 + t];
        __syncthreads();
        float a = 0.f;
        #pragma unroll 8
        for (int f = 0; f < 128; f++) a += sx[f] * Wmg[f*128 + t];
        g_mgg[g*128 + t] = a;
        if (t < 8) {
            float bb = 0.f;
            #pragma unroll 8
            for (int f = 0; f < 128; f++) bb += sx[f] * Wtg[f*8 + t];
            g_tg[g*8 + t] = bb;
        }
    }
}

// f32x2 GEMM inner step: 2 rows (in sA), 4 k-values, cols lane*4..lane*4+3
#define GEMM_CHUNK(Wp, sArow0, sArow1, acc)                                    \
    {                                                                          \
        ulonglong2 w0 = *(const ulonglong2*)&Wp[(k+0)*128 + lane*4];           \
        ulonglong2 w1 = *(const ulonglong2*)&Wp[(k+1)*128 + lane*4];           \
        ulonglong2 w2 = *(const ulonglong2*)&Wp[(k+2)*128 + lane*4];           \
        ulonglong2 w3 = *(const ulonglong2*)&Wp[(k+3)*128 + lane*4];           \
        float4 a0 = *(const float4*)&(sArow0)[k];                              \
        float4 a1 = *(const float4*)&(sArow1)[k];                              \
        unsigned long long p;                                                  \
        p = bcast2(a0.x); fma2(acc[0][0], p, w0.x); fma2(acc[0][1], p, w0.y);  \
        p = bcast2(a0.y); fma2(acc[0][0], p, w1.x); fma2(acc[0][1], p, w1.y);  \
        p = bcast2(a0.z); fma2(acc[0][0], p, w2.x); fma2(acc[0][1], p, w2.y);  \
        p = bcast2(a0.w); fma2(acc[0][0], p, w3.x); fma2(acc[0][1], p, w3.y);  \
        p = bcast2(a1.x); fma2(acc[1][0], p, w0.x); fma2(acc[1][1], p, w0.y);  \
        p = bcast2(a1.y); fma2(acc[1][0], p, w1.x); fma2(acc[1][1], p, w1.y);  \
        p = bcast2(a1.z); fma2(acc[1][0], p, w2.x); fma2(acc[1][1], p, w2.y);  \
        p = bcast2(a1.w); fma2(acc[1][0], p, w3.x); fma2(acc[1][1], p, w3.y);  \
    }

// ---------------- K3: edge projections, f32x2 GEMM + scatter-add ----------------
// grid = En/EPB blocks of 256 threads. Warp w owns edges w*2, w*2+1.
__global__ void k_scatter(const float* __restrict__ eattr, const int* __restrict__ eidx,
                          const float* __restrict__ Wme,
                          const float* __restrict__ Wte1, const float* __restrict__ Wte2,
                          const float* __restrict__ Wte3) {
    __shared__ __align__(16) float sA[EPB][128];
    int t = threadIdx.x, warp = t >> 5, lane = t & 31;
    int e0 = blockIdx.x * EPB;
    int posMain[2], posT[2];
    #pragma unroll
    for (int i = 0; i < 2; i++) {
        int r = warp*2 + i, e = e0 + r;
        *(float4*)&sA[r][lane*4] = *(const float4*)&eattr[e*128 + lane*4];
        int sg = eidx[e], dg = eidx[En + e];
        int b = sg >> 7, s = sg & 127, d = dg & 127;
        posMain[i] = (b*Nn + s)*Nn + d;
        posT[i]    = (b*Nn + d)*Nn + s;
    }
    __syncwarp();
    unsigned long long acc[2][2] = {{0ull,0ull},{0ull,0ull}};
    #pragma unroll 4
    for (int k = 0; k < 128; k += 4)
        GEMM_CHUNK(Wme, sA[warp*2], sA[warp*2+1], acc)
    #pragma unroll
    for (int i = 0; i < 2; i++) {
        float2 v01 = unpack2(acc[i][0]);
        float2 v23 = unpack2(acc[i][1]);
        float* dst = &g_msgE[posMain[i]*128 + lane*4];
        atomicAdd(dst + 0, v01.x);
        atomicAdd(dst + 1, v01.y);
        atomicAdd(dst + 2, v23.x);
        atomicAdd(dst + 3, v23.y);
    }
    if (lane < 24) {
        const float* W = (lane < 8) ? Wte1 : ((lane < 16) ? Wte2 : Wte3);
        int c = lane & 7;
        float acc2[2] = {};
        #pragma unroll 4
        for (int k = 0; k < 128; k += 4) {
            float w0 = W[(k+0)*8 + c], w1 = W[(k+1)*8 + c];
            float w2 = W[(k+2)*8 + c], w3 = W[(k+3)*8 + c];
            #pragma unroll
            for (int i = 0; i < 2; i++) {
                float4 a = *(const float4*)&sA[warp*2 + i][k];
                acc2[i] += a.x*w0 + a.y*w1 + a.z*w2 + a.w*w3;
            }
        }
        #pragma unroll
        for (int i = 0; i < 2; i++) {
            if (lane < 8)       atomicAdd(&g_T1[posT[i]*8 + c], acc2[i]);
            else if (lane < 16) atomicAdd(&g_T2[posT[i]*8 + c], acc2[i]);
            else                atomicAdd(&g_te3[posMain[i]*8 + c], acc2[i]);
        }
    }
}

// ---------------- K4: fused gather+LN1+GEMM1+LN2+GEMM2+atomicMax ----------------
__global__ void k_mpnn(const int* __restrict__ eidx,
                       const float* __restrict__ ln1s, const float* __restrict__ ln1o,
                       const float* __restrict__ W1,
                       const float* __restrict__ ln2s, const float* __restrict__ ln2o,
                       const float* __restrict__ W2) {
    __shared__ __align__(16) float sY[EPB][128];
    int t = threadIdx.x, warp = t >> 5, lane = t & 31;
    int e0 = blockIdx.x * EPB;
    int dglob[2];
    float4 s1 = *(const float4*)&ln1s[lane*4];
    float4 o1 = *(const float4*)&ln1o[lane*4];
    // ---- stage 1: gather + LN1 + ReLU ----
    #pragma unroll
    for (int i = 0; i < 2; i++) {
        int r = warp*2 + i, e = e0 + r;
        int sg = eidx[e], dg = eidx[En + e];
        int b = sg >> 7, s = sg & 127, d = dg & 127;
        dglob[i] = b*Nn + d;
        float4 x  = *(const float4*)&g_msgE[((b*Nn + s)*Nn + d)*128 + lane*4];
        float4 m1 = *(const float4*)&g_msg1[dglob[i]*128 + lane*4];
        float4 m2 = *(const float4*)&g_msg2[(b*Nn + s)*128 + lane*4];
        float4 mg = *(const float4*)&g_mgg[b*128 + lane*4];
        x.x += m1.x + m2.x + mg.x;
        x.y += m1.y + m2.y + mg.y;
        x.z += m1.z + m2.z + mg.z;
        x.w += m1.w + m2.w + mg.w;
        float mean = wredsum(x.x + x.y + x.z + x.w) * (1.f/128.f);
        float dx = x.x - mean, dy = x.y - mean, dz = x.z - mean, dw = x.w - mean;
        float var = wredsum(dx*dx + dy*dy + dz*dz + dw*dw) * (1.f/128.f);
        float rstd = rsqrtf(var + 1e-5f);
        float4 y;
        y.x = fmaxf(s1.x * dx * rstd + o1.x, 0.f);
        y.y = fmaxf(s1.y * dy * rstd + o1.y, 0.f);
        y.z = fmaxf(s1.z * dz * rstd + o1.z, 0.f);
        y.w = fmaxf(s1.w * dw * rstd + o1.w, 0.f);
        *(float4*)&sY[r][lane*4] = y;
    }
    __syncwarp();
    // ---- stage 2: GEMM1 + LN2 + ReLU ----
    float4 s2 = *(const float4*)&ln2s[lane*4];
    float4 o2 = *(const float4*)&ln2o[lane*4];
    {
        unsigned long long acc[2][2] = {{0ull,0ull},{0ull,0ull}};
        #pragma unroll 4
        for (int k = 0; k < 128; k += 4)
            GEMM_CHUNK(W1, sY[warp*2], sY[warp*2+1], acc)
        __syncwarp();
        #pragma unroll
        for (int i = 0; i < 2; i++) {
            float2 v01 = unpack2(acc[i][0]);
            float2 v23 = unpack2(acc[i][1]);
            float mean = wredsum(v01.x + v01.y + v23.x + v23.y) * (1.f/128.f);
            float d0 = v01.x - mean, d1 = v01.y - mean;
            float d2 = v23.x - mean, d3 = v23.y - mean;
            float var = wredsum(d0*d0 + d1*d1 + d2*d2 + d3*d3) * (1.f/128.f);
            float rstd = rsqrtf(var + 1e-5f);
            float4 y;
            y.x = fmaxf(s2.x * d0 * rstd + o2.x, 0.f);
            y.y = fmaxf(s2.y * d1 * rstd + o2.y, 0.f);
            y.z = fmaxf(s2.z * d2 * rstd + o2.z, 0.f);
            y.w = fmaxf(s2.w * d3 * rstd + o2.w, 0.f);
            *(float4*)&sY[warp*2 + i][lane*4] = y;
        }
    }
    __syncwarp();
    // ---- stage 3: GEMM2 + atomicMax ----
    {
        unsigned long long acc[2][2] = {{0ull,0ull},{0ull,0ull}};
        #pragma unroll 4
        for (int k = 0; k < 128; k += 4)
            GEMM_CHUNK(W2, sY[warp*2], sY[warp*2+1], acc)
        #pragma unroll
        for (int i = 0; i < 2; i++) {
            float2 v01 = unpack2(acc[i][0]);
            float2 v23 = unpack2(acc[i][1]);
            unsigned* dst = &g_maxacc[dglob[i]*128 + lane*4];
            atomicMax(dst + 0, fmap(v01.x));
            atomicMax(dst + 1, fmap(v01.y));
            atomicMax(dst + 2, fmap(v23.x));
            atomicMax(dst + 3, fmap(v23.y));
        }
    }
}

// ---------------- K5: triplet max + W_u3 (2 edges per block) ----------------
__global__ void k_tri(const int* __restrict__ eidx, const float* __restrict__ Wu3,
                      float* __restrict__ out2) {
    __shared__ float sw[2][4][8];
    __shared__ float stm[2][8];
    int t = threadIdx.x;
    int sub = t >> 7, tt = t & 127;
    int e = blockIdx.x * 2 + sub;
    int sg = eidx[e], dg = eidx[En + e];
    int b = sg >> 7, j = sg & 127, k = dg & 127;
    int i = tt;
    const float4* t1v = (const float4*)g_t1;
    const float4* T1v = (const float4*)g_T1;
    const float4* T2v = (const float4*)g_T2;
    int ia = (b*Nn + i) * 2;
    int i1 = ((b*Nn + j)*Nn + i) * 2;
    int i2 = ((b*Nn + k)*Nn + i) * 2;
    float4 a0 = t1v[ia],   a1 = t1v[ia+1];
    float4 b0 = T1v[i1],   b1 = T1v[i1+1];
    float4 c0 = T2v[i2],   c1 = T2v[i2+1];
    float v[8];
    v[0] = a0.x + b0.x + c0.x;  v[1] = a0.y + b0.y + c0.y;
    v[2] = a0.z + b0.z + c0.z;  v[3] = a0.w + b0.w + c0.w;
    v[4] = a1.x + b1.x + c1.x;  v[5] = a1.y + b1.y + c1.y;
    v[6] = a1.z + b1.z + c1.z;  v[7] = a1.w + b1.w + c1.w;
    #pragma unroll
    for (int off = 16; off; off >>= 1) {
        #pragma unroll
        for (int f = 0; f < 8; f++)
            v[f] = fmaxf(v[f], __shfl_xor_sync(0xffffffffu, v[f], off));
    }
    if ((tt & 31) == 0) {
        int w = tt >> 5;
        #pragma unroll
        for (int f = 0; f < 8; f++) sw[sub][w][f] = v[f];
    }
    __syncthreads();
    if (tt < 8) {
        float m = fmaxf(fmaxf(sw[sub][0][tt], sw[sub][1][tt]),
                        fmaxf(sw[sub][2][tt], sw[sub][3][tt]));
        m += g_t2[(b*Nn + j)*8 + tt] + g_t3[(b*Nn + k)*8 + tt]
           + g_te3[((b*Nn + j)*Nn + k)*8 + tt] + g_tg[b*8 + tt];
        stm[sub][tt] = m;
    }
    __syncthreads();
    float acc = 0.f;
    #pragma unroll
    for (int f = 0; f < 8; f++) acc += stm[sub][f] * Wu3[f*128 + tt];
    out2[e*128 + tt] = fmaxf(acc, 0.f);
}

// ---------------- K6: final ret = LN(u1 + max @ W_u2) ----------------
__global__ void k_final(const float* __restrict__ Wu2,
                        const float* __restrict__ lnfs, const float* __restrict__ lnfo,
                        float* __restrict__ out1) {
    __shared__ float sm[128];
    __shared__ float sred[4];
    int n = blockIdx.x, t = threadIdx.x;
    sm[t] = funmap(g_maxacc[n*128 + t]);
    __syncthreads();
    float acc = g_u1[n*128 + t];
    #pragma unroll 8
    for (int f = 0; f < 128; f++) acc += sm[f] * Wu2[f*128 + t];
    float mean = brsum(acc, sred, t) * (1.f/128.f);
    float dmu = acc - mean;
    float var = brsum(dmu*dmu, sred, t) * (1.f/128.f);
    out1[n*128 + t] = lnfs[t] * dmu * rsqrtf(var + 1e-5f) + lnfo[t];
}

// ---------------- launch ----------------
extern "C" void kernel_launch(void* const* d_in, const int* in_sizes, int n_in,
                              void* d_out, int out_size) {
    const float* node_fts  = (const float*)d_in[0];
    const float* edge_attr = (const float*)d_in[1];
    const float* graph_fts = (const float*)d_in[2];
    const float* W_tri1 = (const float*)d_in[3];
    const float* W_tri2 = (const float*)d_in[4];
    const float* W_tri3 = (const float*)d_in[5];
    const float* W_te1  = (const float*)d_in[6];
    const float* W_te2  = (const float*)d_in[7];
    const float* W_te3  = (const float*)d_in[8];
    const float* W_tg   = (const float*)d_in[9];
    const float* W_m1   = (const float*)d_in[10];
    const float* W_m2   = (const float*)d_in[11];
    const float* W_me   = (const float*)d_in[12];
    const float* W_mg   = (const float*)d_in[13];
    const float* ln1_s  = (const float*)d_in[14];
    const float* ln1_o  = (const float*)d_in[15];
    const float* W_mlp1 = (const float*)d_in[16];
    const float* ln2_s  = (const float*)d_in[17];
    const float* ln2_o  = (const float*)d_in[18];
    const float* W_mlp2 = (const float*)d_in[19];
    const float* W_u1   = (const float*)d_in[20];
    const float* W_u2   = (const float*)d_in[21];
    const float* W_u3   = (const float*)d_in[22];
    const float* lnf_s  = (const float*)d_in[23];
    const float* lnf_o  = (const float*)d_in[24];
    const int*   eidx   = (const int*)d_in[25];

    float* out1 = (float*)d_out;                 // ret      [512,128]
    float* out2 = out1 + Bn*Nn*Cn;               // tri gath [8192,128]

    int init_total = 3*A4 + B4 + C4;
    k_init<<<(init_total + 255)/256, 256>>>(eidx);
    k_proj<<<Bn*Nn + Bn, 128>>>(node_fts, graph_fts, W_m1, W_m2, W_u1,
                                W_tri1, W_tri2, W_tri3, W_mg, W_tg);
    k_scatter<<<En/EPB, 256>>>(edge_attr, eidx, W_me, W_te1, W_te2, W_te3);
    k_mpnn<<<En/EPB, 256>>>(eidx, ln1_s, ln1_o, W_mlp1, ln2_s, ln2_o, W_mlp2);
    k_tri<<<En/2, 256>>>(eidx, W_u3, out2);
    k_final<<<Bn*Nn, 128>>>(W_u2, lnf_s, lnf_o, out1);
}